// round 7
// baseline (speedup 1.0000x reference)
#include <cuda_runtime.h>
#include <cuda_bf16.h>
#include <cstdint>
#include <cstddef>

// ===========================================================================
// DaConA on GB300 (sm_103 PTX target: mma.sync bf16 HMMA k16).
// BM=256, BN=128, 8 warps 4(m)x2(n), warp tile 64x64 -> LDS:MMA = 1.0.
// pred = MLP(concat(u_indep[r], i_indep[c], (Wt@u[r]+bt)*(Wt@i[c]+bt))) + 3.5
// ===========================================================================

#define NB      131072
#define NUSERS  100000
#define NITEMS  50000
#define DIMC    960
#define DIMS    32

__device__ __nv_bfloat16 g_TU[(size_t)NUSERS * DIMC];
__device__ __nv_bfloat16 g_TI[(size_t)NITEMS * DIMC];
__device__ __nv_bfloat16 g_UIb[(size_t)NUSERS * DIMC];
__device__ __nv_bfloat16 g_IIb[(size_t)NITEMS * DIMC];
__device__ __nv_bfloat16 g_Wtb[(size_t)DIMC * DIMC];
__device__ __nv_bfloat16 g_W1b[512 * 1024];
__device__ __nv_bfloat16 g_W2b[256 * 512];
__device__ __nv_bfloat16 g_W3b[128 * 256];
__device__ __nv_bfloat16 g_F0[(size_t)NB * 1024];
__device__ __nv_bfloat16 g_F1[(size_t)NB * 512];
__device__ __nv_bfloat16 g_F2[(size_t)NB * 256];

__device__ __forceinline__ uint32_t smem_u32(const void* p) {
    uint32_t a;
    asm("{ .reg .u64 t; cvta.to.shared.u64 t, %1; cvt.u32.u64 %0, t; }" : "=r"(a) : "l"(p));
    return a;
}
#define SWZ128(o) ((o) ^ (((o) >> 3) & 0x70))

__device__ __forceinline__ void cp16(uint32_t dst, const void* src, uint32_t sz) {
    asm volatile("cp.async.cg.shared.global [%0], [%1], 16, %2;" :: "r"(dst), "l"(src), "r"(sz));
}
__device__ __forceinline__ uint32_t lds32(uint32_t a) {
    uint32_t v;
    asm volatile("ld.shared.b32 %0, [%1];" : "=r"(v) : "r"(a));
    return v;
}
// D(16x8) += A(16x16,row) * B(16x8,col) ; bf16 inputs, f32 accum
__device__ __forceinline__ void mma16(float* d, const uint32_t* a, const uint32_t* b) {
    asm volatile("mma.sync.aligned.m16n8k16.row.col.f32.bf16.bf16.f32 "
                 "{%0,%1,%2,%3}, {%4,%5,%6,%7}, {%8,%9}, {%0,%1,%2,%3};"
                 : "+f"(d[0]), "+f"(d[1]), "+f"(d[2]), "+f"(d[3])
                 : "r"(a[0]), "r"(a[1]), "r"(a[2]), "r"(a[3]), "r"(b[0]), "r"(b[1]));
}

// ---------------------------------------------------------------------------
// bf16 mma.sync NT GEMM: C[m][n] = act( sum_k A[m][k]*Bw[n][k] + bias[n] )
// BM=256, BN=128, BK=64 bf16 (=128B SW128 rows), 3-stage cp.async pipeline.
// 8 warps: 4(m) x 2(n); warp tile 64x64 (4 mt x 8 nt m16n8k16 tiles).
// FINAL: fuse out[b] = tanh(row) . Wr + br + 3.5 (requires N == 128).
// ---------------------------------------------------------------------------
template<bool TANH, bool OUT_BF16, bool FINAL>
__global__ __launch_bounds__(256) void gemm_bf(
    const __nv_bfloat16* __restrict__ A, const __nv_bfloat16* __restrict__ Bw,
    const float* __restrict__ bias, void* __restrict__ Cv,
    const float* __restrict__ Wr, const float* __restrict__ brp,
    int M, int N, int K)
{
    extern __shared__ char smem[];
    const uint32_t base = smem_u32(smem);
    const int t = threadIdx.x;
    const int wid = t >> 5, lane = t & 31;
    const int wm = wid >> 1;            // 0..3  (64-row quarter)
    const int wn = wid & 1;             // 0..1  (64-col half)
    const int g  = lane >> 2;           // 0..7
    const int q  = lane & 3;            // 0..3

    constexpr int ATILE = 32768;        // 256 rows x 128 B
    constexpr int BTILE = 16384;        // 128 rows x 128 B
    constexpr int SB    = ATILE + BTILE;
    const int bm = blockIdx.y * 256;
    const int bn = blockIdx.x * 128;

    float* biass = (float*)(smem);            // 512 B
    float* wrs   = (float*)(smem + 512);      // 512 B
    float* part  = (float*)(smem + 1024);     // 2048 B (FINAL: 256 rows x 2)
    const uint32_t tiles = (base + 3072 + 1023) & ~1023u;

    for (int j = t; j < 128; j += 256) {
        int gn = bn + j;
        biass[j] = (gn < N) ? bias[gn] : 0.f;
        if (FINAL) wrs[j] = Wr[j];
    }

    const int seg = t & 7;              // 16B segment in a 128B row (8 bf16)
    const int rb  = t >> 3;             // 0..31

    auto load_chunk = [&](int c, int s) {
        const uint32_t at = tiles + s * SB;
        const uint32_t bt_ = at + ATILE;
#pragma unroll
        for (int rr = 0; rr < 8; rr++) {
            int row = rb + rr * 32;
            int gr  = bm + row;
            int ok  = gr < M;
            const __nv_bfloat16* src = A + (size_t)(ok ? gr : 0) * K + c * 64 + seg * 8;
            cp16(at + SWZ128(row * 128 + seg * 16), src, ok ? 16u : 0u);
        }
#pragma unroll
        for (int rr = 0; rr < 4; rr++) {
            int row = rb + rr * 32;
            int gn  = bn + row;
            int ok  = gn < N;
            const __nv_bfloat16* src = Bw + (size_t)(ok ? gn : 0) * K + c * 64 + seg * 8;
            cp16(bt_ + SWZ128(row * 128 + seg * 16), src, ok ? 16u : 0u);
        }
        asm volatile("cp.async.commit_group;" ::: "memory");
    };

    float acc[4][8][4];
#pragma unroll
    for (int i = 0; i < 4; i++)
#pragma unroll
        for (int j = 0; j < 8; j++)
#pragma unroll
            for (int v = 0; v < 4; v++) acc[i][j][v] = 0.f;

    const int NKc = K >> 6;             // K/64 bf16 elems per chunk
    load_chunk(0, 0);
    load_chunk(1, 1);

    for (int i = 0; i < NKc; i++) {
        const int s = i - (i / 3) * 3;  // i % 3
        if (i + 1 < NKc) asm volatile("cp.async.wait_group 1;" ::: "memory");
        else             asm volatile("cp.async.wait_group 0;" ::: "memory");
        __syncthreads();
        if (i + 2 < NKc) {
            int s2 = i + 2; s2 -= (s2 / 3) * 3;
            load_chunk(i + 2, s2);
        }

        const uint32_t a_s = tiles + s * SB;
        const uint32_t b_s = a_s + ATILE;
#pragma unroll
        for (int ks = 0; ks < 4; ks++) {        // 4 x k16 per 128B chunk
            uint32_t af[4][4], bf[8][2];
            const int kc = ks * 32 + q * 4;     // byte col offset of a0/b0
#pragma unroll
            for (int mt = 0; mt < 4; mt++) {
                const int r0 = (wm * 64 + mt * 16 + g) * 128;
                af[mt][0] = lds32(a_s + SWZ128(r0 + kc));
                af[mt][1] = lds32(a_s + SWZ128(r0 + 1024 + kc));
                af[mt][2] = lds32(a_s + SWZ128(r0 + kc + 16));
                af[mt][3] = lds32(a_s + SWZ128(r0 + 1024 + kc + 16));
            }
#pragma unroll
            for (int nt = 0; nt < 8; nt++) {
                const int r0 = (wn * 64 + nt * 8 + g) * 128;
                bf[nt][0] = lds32(b_s + SWZ128(r0 + kc));
                bf[nt][1] = lds32(b_s + SWZ128(r0 + kc + 16));
            }
#pragma unroll
            for (int mt = 0; mt < 4; mt++)
#pragma unroll
                for (int nt = 0; nt < 8; nt++)
                    mma16(acc[mt][nt], af[mt], bf[nt]);
        }
    }
    __syncthreads();

    // ------------------------- epilogue -------------------------
    if (FINAL) {
        // tanh + dot with Wr; reduce q-lanes by shuffle, 2 n-warps via smem.
#pragma unroll
        for (int mt = 0; mt < 4; mt++) {
            float p0 = 0.f, p1 = 0.f;
#pragma unroll
            for (int nt = 0; nt < 8; nt++) {
                const int jc = wn * 64 + nt * 8 + 2 * q;
                const float bx = biass[jc], by = biass[jc + 1];
                const float wx = wrs[jc],  wy = wrs[jc + 1];
                p0 += tanhf(acc[mt][nt][0] + bx) * wx + tanhf(acc[mt][nt][1] + by) * wy;
                p1 += tanhf(acc[mt][nt][2] + bx) * wx + tanhf(acc[mt][nt][3] + by) * wy;
            }
            p0 += __shfl_xor_sync(0xFFFFFFFFu, p0, 1);
            p0 += __shfl_xor_sync(0xFFFFFFFFu, p0, 2);
            p1 += __shfl_xor_sync(0xFFFFFFFFu, p1, 1);
            p1 += __shfl_xor_sync(0xFFFFFFFFu, p1, 2);
            if (q == 0) {
                part[(wm * 64 + mt * 16 + g) * 2 + wn]     = p0;
                part[(wm * 64 + mt * 16 + g + 8) * 2 + wn] = p1;
            }
        }
        __syncthreads();
        {
            float s = part[t * 2] + part[t * 2 + 1];
            if (bm + t < M) ((float*)Cv)[bm + t] = s + brp[0] + 3.5f;
        }
        return;
    }

#pragma unroll
    for (int mt = 0; mt < 4; mt++) {
        const int r0 = bm + wm * 64 + mt * 16 + g;
#pragma unroll
        for (int nt = 0; nt < 8; nt++) {
            const int jc = wn * 64 + nt * 8 + 2 * q;
            const int gn = bn + jc;
            if (gn >= N) continue;
            const float bx = biass[jc], by = biass[jc + 1];
            float x0 = acc[mt][nt][0] + bx, x1 = acc[mt][nt][1] + by;
            float x2 = acc[mt][nt][2] + bx, x3 = acc[mt][nt][3] + by;
            if (TANH) { x0 = tanhf(x0); x1 = tanhf(x1); x2 = tanhf(x2); x3 = tanhf(x3); }
            if (OUT_BF16) {
                __nv_bfloat16* C = (__nv_bfloat16*)Cv;
                if (r0 < M)
                    *(__nv_bfloat162*)(C + (size_t)r0 * N + gn) =
                        __nv_bfloat162(__float2bfloat16(x0), __float2bfloat16(x1));
                if (r0 + 8 < M)
                    *(__nv_bfloat162*)(C + (size_t)(r0 + 8) * N + gn) =
                        __nv_bfloat162(__float2bfloat16(x2), __float2bfloat16(x3));
            } else {
                float* C = (float*)Cv;
                if (r0 < M)     *(float2*)(C + (size_t)r0 * N + gn)       = make_float2(x0, x1);
                if (r0 + 8 < M) *(float2*)(C + (size_t)(r0 + 8) * N + gn) = make_float2(x2, x3);
            }
        }
    }
}

// ---------------------------------------------------------------------------
// fp32 -> bf16 conversion (count divisible by 1024; 4 elems/thread)
// ---------------------------------------------------------------------------
__global__ __launch_bounds__(256) void conv_bf16(
    const float* __restrict__ in, __nv_bfloat16* __restrict__ out)
{
    const size_t i = ((size_t)blockIdx.x * 256 + threadIdx.x) * 4;
    float4 v = *(const float4*)(in + i);
    *(__nv_bfloat162*)(out + i)     = __nv_bfloat162(__float2bfloat16(v.x), __float2bfloat16(v.y));
    *(__nv_bfloat162*)(out + i + 2) = __nv_bfloat162(__float2bfloat16(v.z), __float2bfloat16(v.w));
}

// ---------------------------------------------------------------------------
// Gather + elementwise product + concat into F0[B, 1024] (bf16)
// ---------------------------------------------------------------------------
__global__ __launch_bounds__(256) void build_factor(
    const int* __restrict__ rows, const int* __restrict__ cols,
    const float* __restrict__ uix, const float* __restrict__ iix,
    const __nv_bfloat16* __restrict__ TU, const __nv_bfloat16* __restrict__ TI,
    __nv_bfloat16* __restrict__ F0)
{
    const int b = blockIdx.x;
    const int r = rows[b];
    const int c = cols[b];
    const int f = threadIdx.x * 4;

    float4 v;
    if (f < 32) {
        v = *(const float4*)(uix + (size_t)r * DIMS + f);
    } else if (f < 64) {
        v = *(const float4*)(iix + (size_t)c * DIMS + (f - 32));
    } else {
        const __nv_bfloat162* a = (const __nv_bfloat162*)(TU + (size_t)r * DIMC + (f - 64));
        const __nv_bfloat162* bb = (const __nv_bfloat162*)(TI + (size_t)c * DIMC + (f - 64));
        float2 a0 = __bfloat1622float2(a[0]),  a1 = __bfloat1622float2(a[1]);
        float2 b0 = __bfloat1622float2(bb[0]), b1 = __bfloat1622float2(bb[1]);
        v = make_float4(a0.x * b0.x, a0.y * b0.y, a1.x * b1.x, a1.y * b1.y);
    }
    __nv_bfloat16* o = F0 + (size_t)b * 1024 + f;
    *(__nv_bfloat162*)(o)     = __nv_bfloat162(__float2bfloat16(v.x), __float2bfloat16(v.y));
    *(__nv_bfloat162*)(o + 2) = __nv_bfloat162(__float2bfloat16(v.z), __float2bfloat16(v.w));
}

// ---------------------------------------------------------------------------
extern "C" void kernel_launch(void* const* d_in, const int* in_sizes, int n_in,
                              void* d_out, int out_size)
{
    const int*   rows       = (const int*)d_in[0];
    const int*   cols       = (const int*)d_in[1];
    const float* user_inter = (const float*)d_in[2];
    const float* item_inter = (const float*)d_in[3];
    const float* uix        = (const float*)d_in[4];
    const float* iix        = (const float*)d_in[5];
    const float* Wt         = (const float*)d_in[6];
    const float* bt         = (const float*)d_in[7];
    const float* W1         = (const float*)d_in[8];
    const float* b1         = (const float*)d_in[9];
    const float* W2         = (const float*)d_in[10];
    const float* b2         = (const float*)d_in[11];
    const float* W3         = (const float*)d_in[12];
    const float* b3         = (const float*)d_in[13];
    const float* Wr         = (const float*)d_in[14];
    const float* br         = (const float*)d_in[15];
    float*       out        = (float*)d_out;

    __nv_bfloat16 *TU, *TI, *UIb, *IIb, *Wtb, *W1b, *W2b, *W3b, *F0, *F1, *F2;
    cudaGetSymbolAddress((void**)&TU, g_TU);
    cudaGetSymbolAddress((void**)&TI, g_TI);
    cudaGetSymbolAddress((void**)&UIb, g_UIb);
    cudaGetSymbolAddress((void**)&IIb, g_IIb);
    cudaGetSymbolAddress((void**)&Wtb, g_Wtb);
    cudaGetSymbolAddress((void**)&W1b, g_W1b);
    cudaGetSymbolAddress((void**)&W2b, g_W2b);
    cudaGetSymbolAddress((void**)&W3b, g_W3b);
    cudaGetSymbolAddress((void**)&F0, g_F0);
    cudaGetSymbolAddress((void**)&F1, g_F1);
    cudaGetSymbolAddress((void**)&F2, g_F2);

    // dyn smem: 3072 hdr + 1024 align slack + 3 stages * 48KB
    const int SZ = 3072 + 1024 + 3 * 49152;   // 151552
    cudaFuncSetAttribute(gemm_bf<false, true, false>, cudaFuncAttributeMaxDynamicSharedMemorySize, SZ);
    cudaFuncSetAttribute(gemm_bf<true, true, false>,  cudaFuncAttributeMaxDynamicSharedMemorySize, SZ);
    cudaFuncSetAttribute(gemm_bf<true, false, true>,  cudaFuncAttributeMaxDynamicSharedMemorySize, SZ);

    const dim3 blk(256);

    // 0) fp32 -> bf16 conversions
    conv_bf16<<<(NUSERS * DIMC) / 1024, blk>>>(user_inter, UIb);
    conv_bf16<<<(NITEMS * DIMC) / 1024, blk>>>(item_inter, IIb);
    conv_bf16<<<(DIMC * DIMC) / 1024, blk>>>(Wt, Wtb);
    conv_bf16<<<(512 * 1024) / 1024, blk>>>(W1, W1b);
    conv_bf16<<<(256 * 512) / 1024, blk>>>(W2, W2b);
    conv_bf16<<<(128 * 256) / 1024, blk>>>(W3, W3b);

    // 1) Per-entity transfer transforms (bf16 out), N=960 masked to 8x128
    gemm_bf<false, true, false><<<dim3(8, (NUSERS + 255) / 256), blk, SZ>>>(
        UIb, Wtb, bt, TU, nullptr, nullptr, NUSERS, DIMC, DIMC);
    gemm_bf<false, true, false><<<dim3(8, (NITEMS + 255) / 256), blk, SZ>>>(
        IIb, Wtb, bt, TI, nullptr, nullptr, NITEMS, DIMC, DIMC);

    // 2) Gather + elementwise product + concat (bf16 out)
    build_factor<<<NB, blk>>>(rows, cols, uix, iix, TU, TI, F0);

    // 3) MLP layers; last layer fuses Wr-dot + br + 3.5 into epilogue
    gemm_bf<true, true, false><<<dim3(4, NB / 256), blk, SZ>>>(
        F0, W1b, b1, F1, nullptr, nullptr, NB, 512, 1024);
    gemm_bf<true, true, false><<<dim3(2, NB / 256), blk, SZ>>>(
        F1, W2b, b2, F2, nullptr, nullptr, NB, 256, 512);
    gemm_bf<true, false, true><<<dim3(1, NB / 256), blk, SZ>>>(
        F2, W3b, b3, out, Wr, br, NB, 128, 256);
}

// round 8
// speedup vs baseline: 1.2520x; 1.2520x over previous
#include <cuda_runtime.h>
#include <cuda_bf16.h>
#include <cstdint>
#include <cstddef>

// ===========================================================================
// DaConA on GB300 (sm_103 PTX target: mma.sync bf16 HMMA k16).
// R6 tiling (BM=BN=128, 8 warps 2x4, warp 64x32, 126 regs, 2 CTA/SM) +
// ldmatrix fragment loads with fully hoisted swizzle addressing.
// pred = MLP(concat(u_indep[r], i_indep[c], (Wt@u[r]+bt)*(Wt@i[c]+bt))) + 3.5
// ===========================================================================

#define NB      131072
#define NUSERS  100000
#define NITEMS  50000
#define DIMC    960
#define DIMS    32

__device__ __nv_bfloat16 g_TU[(size_t)NUSERS * DIMC];
__device__ __nv_bfloat16 g_TI[(size_t)NITEMS * DIMC];
__device__ __nv_bfloat16 g_UIb[(size_t)NUSERS * DIMC];
__device__ __nv_bfloat16 g_IIb[(size_t)NITEMS * DIMC];
__device__ __nv_bfloat16 g_Wtb[(size_t)DIMC * DIMC];
__device__ __nv_bfloat16 g_W1b[512 * 1024];
__device__ __nv_bfloat16 g_W2b[256 * 512];
__device__ __nv_bfloat16 g_W3b[128 * 256];
__device__ __nv_bfloat16 g_F0[(size_t)NB * 1024];
__device__ __nv_bfloat16 g_F1[(size_t)NB * 512];
__device__ __nv_bfloat16 g_F2[(size_t)NB * 256];

__device__ __forceinline__ uint32_t smem_u32(const void* p) {
    uint32_t a;
    asm("{ .reg .u64 t; cvta.to.shared.u64 t, %1; cvt.u32.u64 %0, t; }" : "=r"(a) : "l"(p));
    return a;
}
#define SWZ128(o) ((o) ^ (((o) >> 3) & 0x70))

__device__ __forceinline__ void cp16(uint32_t dst, const void* src, uint32_t sz) {
    asm volatile("cp.async.cg.shared.global [%0], [%1], 16, %2;" :: "r"(dst), "l"(src), "r"(sz));
}
__device__ __forceinline__ void ldsm4(uint32_t* r, uint32_t addr) {
    asm volatile("ldmatrix.sync.aligned.m8n8.x4.shared.b16 {%0,%1,%2,%3}, [%4];"
                 : "=r"(r[0]), "=r"(r[1]), "=r"(r[2]), "=r"(r[3]) : "r"(addr));
}
// D(16x8) += A(16x16,row) * B(16x8,col) ; bf16 inputs, f32 accum
__device__ __forceinline__ void mma16(float* d, const uint32_t* a, const uint32_t* b) {
    asm volatile("mma.sync.aligned.m16n8k16.row.col.f32.bf16.bf16.f32 "
                 "{%0,%1,%2,%3}, {%4,%5,%6,%7}, {%8,%9}, {%0,%1,%2,%3};"
                 : "+f"(d[0]), "+f"(d[1]), "+f"(d[2]), "+f"(d[3])
                 : "r"(a[0]), "r"(a[1]), "r"(a[2]), "r"(a[3]), "r"(b[0]), "r"(b[1]));
}

// ---------------------------------------------------------------------------
// bf16 mma.sync NT GEMM: C[m][n] = act( sum_k A[m][k]*Bw[n][k] + bias[n] )
// BM=BN=128, BK=64 bf16 (=128B SW128 rows), 3-stage cp.async pipeline.
// 8 warps: 2(m) x 4(n); warp tile 64x32; ldmatrix w/ hoisted addresses.
// FINAL: fuse out[b] = tanh(row) . Wr + br + 3.5 (requires N == 128).
// ---------------------------------------------------------------------------
template<bool TANH, bool OUT_BF16, bool FINAL>
__global__ __launch_bounds__(256) void gemm_bf(
    const __nv_bfloat16* __restrict__ A, const __nv_bfloat16* __restrict__ Bw,
    const float* __restrict__ bias, void* __restrict__ Cv,
    const float* __restrict__ Wr, const float* __restrict__ brp,
    int M, int N, int K)
{
    extern __shared__ char smem[];
    const uint32_t base = smem_u32(smem);
    const int t = threadIdx.x;
    const int wid = t >> 5, lane = t & 31;
    const int wm = wid >> 2;            // 0..1  (64-row half)
    const int wn = wid & 3;             // 0..3  (32-col quarter)
    const int g  = lane >> 2;           // 0..7
    const int q  = lane & 3;            // 0..3

    constexpr int TILE = 16384;         // 128 rows x 128 B
    constexpr int SB   = 2 * TILE;
    const int bm = blockIdx.y * 128;
    const int bn = blockIdx.x * 128;

    float* biass = (float*)(smem);            // 512 B
    float* wrs   = (float*)(smem + 512);      // 512 B
    float* part  = (float*)(smem + 1024);     // 2048 B (FINAL reduction)
    const uint32_t tiles = (base + 3072 + 1023) & ~1023u;

    for (int j = t; j < 128; j += 256) {
        int gn = bn + j;
        biass[j] = (gn < N) ? bias[gn] : 0.f;
        if (FINAL) wrs[j] = Wr[j];
    }

    const int seg = t & 7;              // 16B segment in a 128B row (8 bf16)
    const int rb  = t >> 3;             // 0..31

    auto load_chunk = [&](int c, int s) {
        const uint32_t at = tiles + s * SB;
        const uint32_t bt_ = at + TILE;
#pragma unroll
        for (int rr = 0; rr < 4; rr++) {
            int row = rb + rr * 32;
            int gr  = bm + row;
            int ok  = gr < M;
            const __nv_bfloat16* src = A + (size_t)(ok ? gr : 0) * K + c * 64 + seg * 8;
            cp16(at + SWZ128(row * 128 + seg * 16), src, ok ? 16u : 0u);
        }
#pragma unroll
        for (int rr = 0; rr < 4; rr++) {
            int row = rb + rr * 32;
            int gn  = bn + row;
            int ok  = gn < N;
            const __nv_bfloat16* src = Bw + (size_t)(ok ? gn : 0) * K + c * 64 + seg * 8;
            cp16(bt_ + SWZ128(row * 128 + seg * 16), src, ok ? 16u : 0u);
        }
        asm volatile("cp.async.commit_group;" ::: "memory");
    };

    float acc[4][4][4];
#pragma unroll
    for (int i = 0; i < 4; i++)
#pragma unroll
        for (int j = 0; j < 4; j++)
#pragma unroll
            for (int v = 0; v < 4; v++) acc[i][j][v] = 0.f;

    // --- hoisted ldmatrix addressing ------------------------------------
    // A: lanes 0-15 -> rows wm*64+mt*16+(lane&15), k-bytes 0-15;
    //    lanes 16-31 -> same rows, k-bytes 16-31 (second k8 half).
    // B: matrix idx lane>>3; rows wn*32+np*16+brow; k-half boff.
    // SWZ128(row*128 + low) = row*128 + (low ^ ((row&7)<<4)) since low<128.
    // mt*16 / np*16 preserve row&7 -> XOR term per-thread constant.
    const int arow = lane & 15;
    const int aoff = (lane >> 4) * 16;
    const int axor = (arow & 7) << 4;
    const int bm8  = lane >> 3;
    const int brow = ((bm8 >> 1) << 3) + (lane & 7);
    const int boff = (bm8 & 1) * 16;
    const int bxor = (lane & 7) << 4;
    uint32_t off_a[4], off_b[4];
#pragma unroll
    for (int ks = 0; ks < 4; ks++) {
        off_a[ks] = (uint32_t)((wm * 64 + arow) * 128 + ((ks * 32 + aoff) ^ axor));
        off_b[ks] = (uint32_t)((wn * 32 + brow) * 128 + ((ks * 32 + boff) ^ bxor)) + TILE;
    }

    const int NKc = K >> 6;             // K/64 bf16 elems per chunk
    load_chunk(0, 0);
    load_chunk(1, 1);

    for (int i = 0; i < NKc; i++) {
        const int s = i - (i / 3) * 3;  // i % 3
        if (i + 1 < NKc) asm volatile("cp.async.wait_group 1;" ::: "memory");
        else             asm volatile("cp.async.wait_group 0;" ::: "memory");
        __syncthreads();
        if (i + 2 < NKc) {
            int s2 = i + 2; s2 -= (s2 / 3) * 3;
            load_chunk(i + 2, s2);
        }

        const uint32_t st = tiles + s * SB;
#pragma unroll
        for (int ks = 0; ks < 4; ks++) {        // 4 x k16 per 128B chunk
            uint32_t af[4][4], bf[4][2];
            const uint32_t ab = st + off_a[ks];
            const uint32_t bb = st + off_b[ks];
#pragma unroll
            for (int mt = 0; mt < 4; mt++)
                ldsm4(af[mt], ab + mt * 2048);
#pragma unroll
            for (int np = 0; np < 2; np++) {
                uint32_t r[4];
                ldsm4(r, bb + np * 2048);
                bf[2 * np][0] = r[0]; bf[2 * np][1] = r[1];
                bf[2 * np + 1][0] = r[2]; bf[2 * np + 1][1] = r[3];
            }
#pragma unroll
            for (int mt = 0; mt < 4; mt++)
#pragma unroll
                for (int nt = 0; nt < 4; nt++)
                    mma16(acc[mt][nt], af[mt], bf[nt]);
        }
    }
    __syncthreads();

    // ------------------------- epilogue -------------------------
    if (FINAL) {
#pragma unroll
        for (int mt = 0; mt < 4; mt++) {
            float p0 = 0.f, p1 = 0.f;
#pragma unroll
            for (int nt = 0; nt < 4; nt++) {
                const int jc = wn * 32 + nt * 8 + 2 * q;
                const float bx = biass[jc], by = biass[jc + 1];
                const float wx = wrs[jc],  wy = wrs[jc + 1];
                p0 += tanhf(acc[mt][nt][0] + bx) * wx + tanhf(acc[mt][nt][1] + by) * wy;
                p1 += tanhf(acc[mt][nt][2] + bx) * wx + tanhf(acc[mt][nt][3] + by) * wy;
            }
            p0 += __shfl_xor_sync(0xFFFFFFFFu, p0, 1);
            p0 += __shfl_xor_sync(0xFFFFFFFFu, p0, 2);
            p1 += __shfl_xor_sync(0xFFFFFFFFu, p1, 1);
            p1 += __shfl_xor_sync(0xFFFFFFFFu, p1, 2);
            if (q == 0) {
                part[(wm * 64 + mt * 16 + g) * 4 + wn]     = p0;
                part[(wm * 64 + mt * 16 + g + 8) * 4 + wn] = p1;
            }
        }
        __syncthreads();
        if (t < 128) {
            float s = part[t * 4] + part[t * 4 + 1] + part[t * 4 + 2] + part[t * 4 + 3];
            if (bm + t < M) ((float*)Cv)[bm + t] = s + brp[0] + 3.5f;
        }
        return;
    }

#pragma unroll
    for (int mt = 0; mt < 4; mt++) {
        const int r0 = bm + wm * 64 + mt * 16 + g;
#pragma unroll
        for (int nt = 0; nt < 4; nt++) {
            const int jc = wn * 32 + nt * 8 + 2 * q;
            const int gn = bn + jc;
            if (gn >= N) continue;
            const float bx = biass[jc], by = biass[jc + 1];
            float x0 = acc[mt][nt][0] + bx, x1 = acc[mt][nt][1] + by;
            float x2 = acc[mt][nt][2] + bx, x3 = acc[mt][nt][3] + by;
            if (TANH) { x0 = tanhf(x0); x1 = tanhf(x1); x2 = tanhf(x2); x3 = tanhf(x3); }
            if (OUT_BF16) {
                __nv_bfloat16* C = (__nv_bfloat16*)Cv;
                if (r0 < M)
                    *(__nv_bfloat162*)(C + (size_t)r0 * N + gn) =
                        __nv_bfloat162(__float2bfloat16(x0), __float2bfloat16(x1));
                if (r0 + 8 < M)
                    *(__nv_bfloat162*)(C + (size_t)(r0 + 8) * N + gn) =
                        __nv_bfloat162(__float2bfloat16(x2), __float2bfloat16(x3));
            } else {
                float* C = (float*)Cv;
                if (r0 < M)     *(float2*)(C + (size_t)r0 * N + gn)       = make_float2(x0, x1);
                if (r0 + 8 < M) *(float2*)(C + (size_t)(r0 + 8) * N + gn) = make_float2(x2, x3);
            }
        }
    }
}

// ---------------------------------------------------------------------------
// fp32 -> bf16 conversions.  Exactly TWO launches so launch #6 = W1 GEMM
// (the ncu capture is pinned at -s 5 -c 1).
// ---------------------------------------------------------------------------
__device__ __forceinline__ void conv_blk(const float* src, __nv_bfloat16* dst, size_t blk) {
    const size_t i = blk * 1024 + threadIdx.x * 4;
    float4 v = *(const float4*)(src + i);
    *(__nv_bfloat162*)(dst + i)     = __nv_bfloat162(__float2bfloat16(v.x), __float2bfloat16(v.y));
    *(__nv_bfloat162*)(dst + i + 2) = __nv_bfloat162(__float2bfloat16(v.z), __float2bfloat16(v.w));
}

__global__ __launch_bounds__(256) void conv_user(
    const float* __restrict__ in, __nv_bfloat16* __restrict__ out)
{
    conv_blk(in, out, blockIdx.x);
}

// item_inter(46875 blks) | Wt(900) | W1(512) | W2(128) | W3(32)
__global__ __launch_bounds__(256) void conv_rest(
    const float* __restrict__ item, const float* __restrict__ Wt,
    const float* __restrict__ W1, const float* __restrict__ W2,
    const float* __restrict__ W3,
    __nv_bfloat16* __restrict__ IIb, __nv_bfloat16* __restrict__ Wtb,
    __nv_bfloat16* __restrict__ W1b, __nv_bfloat16* __restrict__ W2b,
    __nv_bfloat16* __restrict__ W3b)
{
    const int b = blockIdx.x;
    if      (b < 46875) conv_blk(item, IIb, b);
    else if (b < 47775) conv_blk(Wt,  Wtb, b - 46875);
    else if (b < 48287) conv_blk(W1,  W1b, b - 47775);
    else if (b < 48415) conv_blk(W2,  W2b, b - 48287);
    else                conv_blk(W3,  W3b, b - 48415);
}

// ---------------------------------------------------------------------------
// Gather + elementwise product + concat into F0[B, 1024] (bf16)
// ---------------------------------------------------------------------------
__global__ __launch_bounds__(256) void build_factor(
    const int* __restrict__ rows, const int* __restrict__ cols,
    const float* __restrict__ uix, const float* __restrict__ iix,
    const __nv_bfloat16* __restrict__ TU, const __nv_bfloat16* __restrict__ TI,
    __nv_bfloat16* __restrict__ F0)
{
    const int b = blockIdx.x;
    const int r = rows[b];
    const int c = cols[b];
    const int f = threadIdx.x * 4;

    float4 v;
    if (f < 32) {
        v = *(const float4*)(uix + (size_t)r * DIMS + f);
    } else if (f < 64) {
        v = *(const float4*)(iix + (size_t)c * DIMS + (f - 32));
    } else {
        const __nv_bfloat162* a = (const __nv_bfloat162*)(TU + (size_t)r * DIMC + (f - 64));
        const __nv_bfloat162* bb = (const __nv_bfloat162*)(TI + (size_t)c * DIMC + (f - 64));
        float2 a0 = __bfloat1622float2(a[0]),  a1 = __bfloat1622float2(a[1]);
        float2 b0 = __bfloat1622float2(bb[0]), b1 = __bfloat1622float2(bb[1]);
        v = make_float4(a0.x * b0.x, a0.y * b0.y, a1.x * b1.x, a1.y * b1.y);
    }
    __nv_bfloat16* o = F0 + (size_t)b * 1024 + f;
    *(__nv_bfloat162*)(o)     = __nv_bfloat162(__float2bfloat16(v.x), __float2bfloat16(v.y));
    *(__nv_bfloat162*)(o + 2) = __nv_bfloat162(__float2bfloat16(v.z), __float2bfloat16(v.w));
}

// ---------------------------------------------------------------------------
extern "C" void kernel_launch(void* const* d_in, const int* in_sizes, int n_in,
                              void* d_out, int out_size)
{
    const int*   rows       = (const int*)d_in[0];
    const int*   cols       = (const int*)d_in[1];
    const float* user_inter = (const float*)d_in[2];
    const float* item_inter = (const float*)d_in[3];
    const float* uix        = (const float*)d_in[4];
    const float* iix        = (const float*)d_in[5];
    const float* Wt         = (const float*)d_in[6];
    const float* bt         = (const float*)d_in[7];
    const float* W1         = (const float*)d_in[8];
    const float* b1         = (const float*)d_in[9];
    const float* W2         = (const float*)d_in[10];
    const float* b2         = (const float*)d_in[11];
    const float* W3         = (const float*)d_in[12];
    const float* b3         = (const float*)d_in[13];
    const float* Wr         = (const float*)d_in[14];
    const float* br         = (const float*)d_in[15];
    float*       out        = (float*)d_out;

    __nv_bfloat16 *TU, *TI, *UIb, *IIb, *Wtb, *W1b, *W2b, *W3b, *F0, *F1, *F2;
    cudaGetSymbolAddress((void**)&TU, g_TU);
    cudaGetSymbolAddress((void**)&TI, g_TI);
    cudaGetSymbolAddress((void**)&UIb, g_UIb);
    cudaGetSymbolAddress((void**)&IIb, g_IIb);
    cudaGetSymbolAddress((void**)&Wtb, g_Wtb);
    cudaGetSymbolAddress((void**)&W1b, g_W1b);
    cudaGetSymbolAddress((void**)&W2b, g_W2b);
    cudaGetSymbolAddress((void**)&W3b, g_W3b);
    cudaGetSymbolAddress((void**)&F0, g_F0);
    cudaGetSymbolAddress((void**)&F1, g_F1);
    cudaGetSymbolAddress((void**)&F2, g_F2);

    const int SZ = 3072 + 1024 + 3 * 32768;   // 102400
    cudaFuncSetAttribute(gemm_bf<false, true, false>, cudaFuncAttributeMaxDynamicSharedMemorySize, SZ);
    cudaFuncSetAttribute(gemm_bf<true, true, false>,  cudaFuncAttributeMaxDynamicSharedMemorySize, SZ);
    cudaFuncSetAttribute(gemm_bf<true, false, true>,  cudaFuncAttributeMaxDynamicSharedMemorySize, SZ);

    const dim3 blk(256);

    // 0) fp32 -> bf16 conversions (2 launches)
    conv_user<<<(NUSERS * DIMC) / 1024, blk>>>(user_inter, UIb);
    conv_rest<<<48447, blk>>>(item_inter, Wt, W1, W2, W3, IIb, Wtb, W1b, W2b, W3b);

    // 1) Per-entity transfer transforms (bf16 out)        [launches 3,4]
    gemm_bf<false, true, false><<<dim3(8, (NUSERS + 127) / 128), blk, SZ>>>(
        UIb, Wtb, bt, TU, nullptr, nullptr, NUSERS, DIMC, DIMC);
    gemm_bf<false, true, false><<<dim3(8, (NITEMS + 127) / 128), blk, SZ>>>(
        IIb, Wtb, bt, TI, nullptr, nullptr, NITEMS, DIMC, DIMC);

    // 2) Gather + elementwise product + concat (bf16 out) [launch 5]
    build_factor<<<NB, blk>>>(rows, cols, uix, iix, TU, TI, F0);

    // 3) MLP layers; W1 is launch #6 (ncu -s 5 target)
    gemm_bf<true, true, false><<<dim3(4, NB / 128), blk, SZ>>>(
        F0, W1b, b1, F1, nullptr, nullptr, NB, 512, 1024);
    gemm_bf<true, true, false><<<dim3(2, NB / 128), blk, SZ>>>(
        F1, W2b, b2, F2, nullptr, nullptr, NB, 256, 512);
    gemm_bf<true, false, true><<<dim3(1, NB / 128), blk, SZ>>>(
        F2, W3b, b3, out, Wr, br, NB, 128, 256);
}